// round 13
// baseline (speedup 1.0000x reference)
#include <cuda_runtime.h>
#include <cuda_bf16.h>
#include <math.h>

#define Bn 16
#define Nn 2048
#define Fn 64
#define Tn 32
#define CHUNKS 128             // chunks per batch
#define NC (Nn / CHUNKS)       // 16 nodes per chunk
#define NBLK (Bn * CHUNKS)     // 2048 reduce blocks
#define SPB 8                  // epilogue blocks per batch
#define SCOLS (Tn / SPB)       // 4 s-columns per epilogue block

// Final sums, accumulated by atomics: [b][0=lhs1(f,t), 1=R2(f,s)]  (256 KB)
// Zero at module load; last epilogue block per batch re-zeroes -> replay-safe.
__device__ float g_sum[Bn][2 * Fn * Tn];
// Per-batch read-completion counters for the zero-reset protocol.
__device__ int g_done[Bn];

__device__ __forceinline__ void f4fma(float4& a, float s, const float4& v) {
    a.x = fmaf(s, v.x, a.x); a.y = fmaf(s, v.y, a.y);
    a.z = fmaf(s, v.z, a.z); a.w = fmaf(s, v.w, a.w);
}

// ---------------------------------------------------------------------------
// Pass 1: stream x once (256 MB) with LDG.128 for 4x bytes-in-flight.
// Thread: q = lane&7 -> t-quad [4q,4q+4); f0 = 4w + (lane>>3), f1 = f0+32.
// Per node (barrier-free over all 16):
//   2x LDG.128; accL0/1 += U1[n]*v; rp = U3[f0]*v0 + U3[f1]*v1;
//   warp-reduce rp over the 4 fr-lanes (xor 8,16); lanes<8 stage red[nn][w][q].
// One barrier; Phase B: rsum over warps, accR += U2[f,n]*rsum; REDG commit.
// ---------------------------------------------------------------------------
__global__ __launch_bounds__(256, 5)
void reduce_kernel(const float* __restrict__ x,
                   const float* __restrict__ U1,
                   const float* __restrict__ U2,
                   const float* __restrict__ U3)
{
    const int blk  = blockIdx.x;        // 0..NBLK-1
    const int b    = blk >> 7;          // / CHUNKS
    const int c    = blk & (CHUNKS - 1);
    const int n0   = c * NC;
    const int tid  = threadIdx.x;
    const int w    = tid >> 5;          // warp 0..7
    const int lane = tid & 31;
    const int q    = lane & 7;          // t-quad
    const int f0   = 4 * w + (lane >> 3);
    const int f1   = f0 + 32;
    const int tq4  = 4 * q;

    __shared__ float  U2s[NC][Fn];      // 4 KB
    __shared__ float  U3s[Fn];
    __shared__ float  U1s[NC];
    __shared__ float4 red[NC][8][8];    // 8 KB: warp-partials of r per t-quad
    __shared__ float4 rsum[NC][8];      // 512 B

    if (tid < Fn) U3s[tid] = U3[tid];
    if (tid < NC) U1s[tid] = U1[n0 + tid];
    for (int i = tid; i < NC * Fn; i += 256) {
        int f  = i >> 4;                // i / NC  (NC == 16)
        int nn = i & (NC - 1);
        U2s[nn][f] = U2[f * Nn + n0 + nn];
    }
    __syncthreads();

    float4 accL0 = make_float4(0.f, 0.f, 0.f, 0.f);
    float4 accL1 = make_float4(0.f, 0.f, 0.f, 0.f);

    const float* xb = x + ((size_t)b * Nn + n0) * (Fn * Tn);
    const float u3a = U3s[f0];
    const float u3b = U3s[f1];

    // ---- Phase A: barrier-free streaming over 16 nodes (LDG.128) ----
#pragma unroll 2
    for (int nn = 0; nn < NC; nn++) {
        const float* xn = xb + (size_t)nn * (Fn * Tn);
        float4 v0 = *(const float4*)(xn + f0 * Tn + tq4);
        float4 v1 = *(const float4*)(xn + f1 * Tn + tq4);

        const float u1n = U1s[nn];
        f4fma(accL0, u1n, v0);
        f4fma(accL1, u1n, v1);

        float4 rp;
        rp.x = fmaf(u3a, v0.x, u3b * v1.x);
        rp.y = fmaf(u3a, v0.y, u3b * v1.y);
        rp.z = fmaf(u3a, v0.z, u3b * v1.z);
        rp.w = fmaf(u3a, v0.w, u3b * v1.w);
        // reduce over the warp's 4 fr-lanes (xor 8, then 16)
        rp.x += __shfl_xor_sync(0xffffffffu, rp.x, 8);
        rp.y += __shfl_xor_sync(0xffffffffu, rp.y, 8);
        rp.z += __shfl_xor_sync(0xffffffffu, rp.z, 8);
        rp.w += __shfl_xor_sync(0xffffffffu, rp.w, 8);
        rp.x += __shfl_xor_sync(0xffffffffu, rp.x, 16);
        rp.y += __shfl_xor_sync(0xffffffffu, rp.y, 16);
        rp.z += __shfl_xor_sync(0xffffffffu, rp.z, 16);
        rp.w += __shfl_xor_sync(0xffffffffu, rp.w, 16);
        if (lane < 8) red[nn][w][lane] = rp;
    }
    __syncthreads();

    // ---- Phase B1: rsum[nn][q] = sum_w red[nn][w][q]  (128 float4) ----
    if (tid < NC * 8) {
        int nn = tid >> 3;
        int qq = tid & 7;
        float4 s = red[nn][0][qq];
#pragma unroll
        for (int w2 = 1; w2 < 8; w2++) {
            float4 v = red[nn][w2][qq];
            s.x += v.x; s.y += v.y; s.z += v.z; s.w += v.w;
        }
        rsum[nn][qq] = s;
    }
    __syncthreads();

    // ---- Phase B2: accR accumulation ----
    float4 accR0 = make_float4(0.f, 0.f, 0.f, 0.f);
    float4 accR1 = make_float4(0.f, 0.f, 0.f, 0.f);
#pragma unroll
    for (int nn = 0; nn < NC; nn++) {
        const float4 rt = rsum[nn][q];
        f4fma(accR0, U2s[nn][f0], rt);
        f4fma(accR1, U2s[nn][f1], rt);
    }

    // ---- Commit: REDG atomic accumulation into g_sum ----
    float* gl = &g_sum[b][0];
    float* gr = &g_sum[b][Fn * Tn];
    atomicAdd(gl + f0 * Tn + tq4 + 0, accL0.x);
    atomicAdd(gl + f0 * Tn + tq4 + 1, accL0.y);
    atomicAdd(gl + f0 * Tn + tq4 + 2, accL0.z);
    atomicAdd(gl + f0 * Tn + tq4 + 3, accL0.w);
    atomicAdd(gl + f1 * Tn + tq4 + 0, accL1.x);
    atomicAdd(gl + f1 * Tn + tq4 + 1, accL1.y);
    atomicAdd(gl + f1 * Tn + tq4 + 2, accL1.z);
    atomicAdd(gl + f1 * Tn + tq4 + 3, accL1.w);
    atomicAdd(gr + f0 * Tn + tq4 + 0, accR0.x);
    atomicAdd(gr + f0 * Tn + tq4 + 1, accR0.y);
    atomicAdd(gr + f0 * Tn + tq4 + 2, accR0.z);
    atomicAdd(gr + f0 * Tn + tq4 + 3, accR0.w);
    atomicAdd(gr + f1 * Tn + tq4 + 0, accR1.x);
    atomicAdd(gr + f1 * Tn + tq4 + 1, accR1.y);
    atomicAdd(gr + f1 * Tn + tq4 + 2, accR1.z);
    atomicAdd(gr + f1 * Tn + tq4 + 3, accR1.w);
}

// ---------------------------------------------------------------------------
// Pass 2: epilogue (R11-proven version, plain launch, no PDL).
// Grid = Bn*SPB = 128 blocks, 128 threads; warp w owns s = g*SCOLS + w.
// ---------------------------------------------------------------------------
__global__ __launch_bounds__(128)
void epilogue_kernel(const float* __restrict__ b_e,
                     const float* __restrict__ V_e,
                     float* __restrict__ out)
{
    const int blk  = blockIdx.x;        // 0..127
    const int b    = blk >> 3;          // / SPB
    const int g    = blk & (SPB - 1);
    const int tid  = threadIdx.x;
    const int w    = tid >> 5;          // warp 0..3 -> s_local
    const int lane = tid & 31;
    const int sbase = g * SCOLS;

    __shared__ float Lss[Fn * Tn];      // lhs1[f][t]  (8 KB)
    __shared__ float Rcol[SCOLS][Fn];   // R2[f][sbase+w]
    __shared__ float VeT[Tn * Tn];      // VeT[t][u]   (4 KB)
    __shared__ float sig[SCOLS][Tn];
    __shared__ int   s_zero;

    float* gs = &g_sum[b][0];

    for (int i = tid; i < Fn * Tn / 4; i += 128)
        ((float4*)Lss)[i] = ((const float4*)gs)[i];
    for (int i = tid; i < SCOLS * Fn; i += 128) {
        int ww = i >> 6;                // s_local
        int f  = i & 63;
        Rcol[ww][f] = gs[Fn * Tn + f * Tn + sbase + ww];
    }
    for (int i = tid; i < Tn * Tn; i += 128) {
        int u = i >> 5, t = i & 31;
        VeT[t * Tn + u] = V_e[i];       // transpose
    }
    __syncthreads();                    // all g_sum reads complete

    if (tid == 0) {
        int old = atomicAdd(&g_done[b], 1);
        s_zero = (old == SPB - 1);
        if (s_zero) g_done[b] = 0;      // reset counter for next replay
    }

    // product + sigmoid: warp w -> s = sbase + w, lane = t
    const int s = sbase + w;
    {
        float p = 0.f;
#pragma unroll
        for (int f = 0; f < Fn; f++)
            p = fmaf(Lss[f * Tn + lane], Rcol[w][f], p);
        p += b_e[lane * Tn + s];
        sig[w][lane] = 1.f / (1.f + expf(-p));
    }
    __syncthreads();                    // also publishes s_zero

    // E + column softmax over u: lane = u
    {
        float e = 0.f;
#pragma unroll
        for (int t = 0; t < Tn; t++)
            e = fmaf(VeT[t * Tn + lane], sig[w][t], e);

        float m = e;
#pragma unroll
        for (int o = 16; o; o >>= 1)
            m = fmaxf(m, __shfl_xor_sync(0xffffffffu, m, o));
        float ex = expf(e - m);
        float ssum = ex;
#pragma unroll
        for (int o = 16; o; o >>= 1)
            ssum += __shfl_xor_sync(0xffffffffu, ssum, o);

        out[b * Tn * Tn + lane * Tn + s] = ex / ssum;
    }

    // Last block of this batch zeroes g_sum[b] (all readers already done).
    if (s_zero) {
        float4 z = make_float4(0.f, 0.f, 0.f, 0.f);
        for (int i = tid; i < 2 * Fn * Tn / 4; i += 128)
            ((float4*)gs)[i] = z;
    }
}

extern "C" void kernel_launch(void* const* d_in, const int* in_sizes, int n_in,
                              void* d_out, int out_size)
{
    const float* x   = (const float*)d_in[0];
    const float* U1  = (const float*)d_in[1];
    const float* U2  = (const float*)d_in[2];
    const float* U3  = (const float*)d_in[3];
    const float* b_e = (const float*)d_in[4];
    const float* V_e = (const float*)d_in[5];
    float* out = (float*)d_out;

    reduce_kernel<<<NBLK, 256>>>(x, U1, U2, U3);
    epilogue_kernel<<<Bn * SPB, 128>>>(b_e, V_e, out);
}

// round 14
// speedup vs baseline: 1.4814x; 1.4814x over previous
#include <cuda_runtime.h>
#include <cuda_bf16.h>
#include <math.h>

#define Bn 16
#define Nn 2048
#define Fn 64
#define Tn 32
#define CHUNKS 128             // chunks per batch
#define NC (Nn / CHUNKS)       // 16 nodes per chunk
#define NBLK (Bn * CHUNKS)     // 2048 reduce blocks
#define SPB 8                  // epilogue blocks per batch
#define SCOLS (Tn / SPB)       // 4 s-columns per epilogue block

// Final sums, accumulated by atomics: [b][0=lhs1(f,t), 1=R2(f,s)]  (256 KB)
// Zero at module load; last epilogue block per batch re-zeroes -> replay-safe.
__device__ float g_sum[Bn][2 * Fn * Tn];
// Per-batch read-completion counters for the zero-reset protocol.
__device__ int g_done[Bn];

// ---------------------------------------------------------------------------
// Pass 1 (R9-proven scalar mainloop; only deltas: unroll 4 + __ldcs stream).
// Barrier-free over 16 nodes, one barrier, cross-warp r-reduction, R2
// accumulation, REDG atomic commit into g_sum.
// Warp w owns f in [8w, 8w+8); lane = t. Coalesced 128B LDG.32.
// ---------------------------------------------------------------------------
__global__ __launch_bounds__(256, 5)
void reduce_kernel(const float* __restrict__ x,
                   const float* __restrict__ U1,
                   const float* __restrict__ U2,
                   const float* __restrict__ U3)
{
    const int blk  = blockIdx.x;        // 0..NBLK-1
    const int b    = blk >> 7;          // / CHUNKS
    const int c    = blk & (CHUNKS - 1);
    const int n0   = c * NC;
    const int tid  = threadIdx.x;
    const int w    = tid >> 5;          // warp 0..7
    const int lane = tid & 31;          // = t

    __shared__ float U2s[NC][Fn];       // U2s[nn][f] = U2[f*N + n0+nn]
    __shared__ float U3s[Fn];
    __shared__ float U1s[NC];
    __shared__ float red[NC][8][32];    // warp-partials of r  (16 KB)
    __shared__ float rsum[NC][32];      // reduced r           (2 KB)

    if (tid < Fn) U3s[tid] = U3[tid];
    if (tid < NC) U1s[tid] = U1[n0 + tid];
    for (int i = tid; i < NC * Fn; i += 256) {
        int f  = i >> 4;                // i / NC  (NC == 16)
        int nn = i & (NC - 1);
        U2s[nn][f] = U2[f * Nn + n0 + nn];
    }
    __syncthreads();

    float accL[8];
#pragma unroll
    for (int j = 0; j < 8; j++) accL[j] = 0.f;

    const float* xb = x + ((size_t)b * Nn + n0) * (Fn * Tn);
    const int fbase = w * 8;
    float u3r[8];
#pragma unroll
    for (int j = 0; j < 8; j++) u3r[j] = U3s[fbase + j];

    // ---- Phase A: barrier-free streaming over 16 nodes ----
#pragma unroll 4
    for (int nn = 0; nn < NC; nn++) {
        const float* xn = xb + (size_t)nn * (Fn * Tn) + fbase * Tn + lane;
        float v[8];
#pragma unroll
        for (int j = 0; j < 8; j++)
            v[j] = __ldcs(xn + j * Tn);   // streaming: evict-first in L2

        const float u1n = U1s[nn];
        float r = 0.f;
#pragma unroll
        for (int j = 0; j < 8; j++) {
            accL[j] = fmaf(u1n, v[j], accL[j]);
            r = fmaf(u3r[j], v[j], r);
        }
        red[nn][w][lane] = r;
    }
    __syncthreads();

    // ---- Phase B: reduce r across warps, then R2 accumulation ----
#pragma unroll
    for (int h = 0; h < 2; h++) {
        int i  = tid + h * 256;
        int nn = i >> 5;
        int t  = i & 31;
        float s = 0.f;
#pragma unroll
        for (int w2 = 0; w2 < 8; w2++) s += red[nn][w2][t];
        rsum[nn][t] = s;
    }
    __syncthreads();

    float accR[8];
#pragma unroll
    for (int j = 0; j < 8; j++) accR[j] = 0.f;
#pragma unroll
    for (int nn = 0; nn < NC; nn++) {
        const float rt = rsum[nn][lane];
#pragma unroll
        for (int j = 0; j < 8; j++)
            accR[j] = fmaf(U2s[nn][fbase + j], rt, accR[j]);
    }

    // ---- Commit: REDG atomic accumulation into the 256 KB g_sum ----
    float* gl = &g_sum[b][0];
    float* gr = &g_sum[b][Fn * Tn];
#pragma unroll
    for (int j = 0; j < 8; j++) {
        atomicAdd(gl + (fbase + j) * Tn + lane, accL[j]);
        atomicAdd(gr + (fbase + j) * Tn + lane, accR[j]);
    }
}

// ---------------------------------------------------------------------------
// Pass 2: epilogue (R11-proven version, plain launch).
// Grid = Bn*SPB = 128 blocks, 128 threads; warp w owns s = g*SCOLS + w.
// ---------------------------------------------------------------------------
__global__ __launch_bounds__(128)
void epilogue_kernel(const float* __restrict__ b_e,
                     const float* __restrict__ V_e,
                     float* __restrict__ out)
{
    const int blk  = blockIdx.x;        // 0..127
    const int b    = blk >> 3;          // / SPB
    const int g    = blk & (SPB - 1);
    const int tid  = threadIdx.x;
    const int w    = tid >> 5;          // warp 0..3 -> s_local
    const int lane = tid & 31;
    const int sbase = g * SCOLS;

    __shared__ float Lss[Fn * Tn];      // lhs1[f][t]  (8 KB)
    __shared__ float Rcol[SCOLS][Fn];   // R2[f][sbase+w]
    __shared__ float VeT[Tn * Tn];      // VeT[t][u]   (4 KB)
    __shared__ float sig[SCOLS][Tn];
    __shared__ int   s_zero;

    float* gs = &g_sum[b][0];

    for (int i = tid; i < Fn * Tn / 4; i += 128)
        ((float4*)Lss)[i] = ((const float4*)gs)[i];
    for (int i = tid; i < SCOLS * Fn; i += 128) {
        int ww = i >> 6;                // s_local
        int f  = i & 63;
        Rcol[ww][f] = gs[Fn * Tn + f * Tn + sbase + ww];
    }
    for (int i = tid; i < Tn * Tn; i += 128) {
        int u = i >> 5, t = i & 31;
        VeT[t * Tn + u] = V_e[i];       // transpose
    }
    __syncthreads();                    // all g_sum reads complete

    if (tid == 0) {
        int old = atomicAdd(&g_done[b], 1);
        s_zero = (old == SPB - 1);
        if (s_zero) g_done[b] = 0;      // reset counter for next replay
    }

    // product + sigmoid: warp w -> s = sbase + w, lane = t
    const int s = sbase + w;
    {
        float p = 0.f;
#pragma unroll
        for (int f = 0; f < Fn; f++)
            p = fmaf(Lss[f * Tn + lane], Rcol[w][f], p);
        p += b_e[lane * Tn + s];
        sig[w][lane] = 1.f / (1.f + expf(-p));
    }
    __syncthreads();                    // also publishes s_zero

    // E + column softmax over u: lane = u
    {
        float e = 0.f;
#pragma unroll
        for (int t = 0; t < Tn; t++)
            e = fmaf(VeT[t * Tn + lane], sig[w][t], e);

        float m = e;
#pragma unroll
        for (int o = 16; o; o >>= 1)
            m = fmaxf(m, __shfl_xor_sync(0xffffffffu, m, o));
        float ex = expf(e - m);
        float ssum = ex;
#pragma unroll
        for (int o = 16; o; o >>= 1)
            ssum += __shfl_xor_sync(0xffffffffu, ssum, o);

        out[b * Tn * Tn + lane * Tn + s] = ex / ssum;
    }

    // Last block of this batch zeroes g_sum[b] (all readers already done).
    if (s_zero) {
        float4 z = make_float4(0.f, 0.f, 0.f, 0.f);
        for (int i = tid; i < 2 * Fn * Tn / 4; i += 128)
            ((float4*)gs)[i] = z;
    }
}

extern "C" void kernel_launch(void* const* d_in, const int* in_sizes, int n_in,
                              void* d_out, int out_size)
{
    const float* x   = (const float*)d_in[0];
    const float* U1  = (const float*)d_in[1];
    const float* U2  = (const float*)d_in[2];
    const float* U3  = (const float*)d_in[3];
    const float* b_e = (const float*)d_in[4];
    const float* V_e = (const float*)d_in[5];
    float* out = (float*)d_out;

    reduce_kernel<<<NBLK, 256>>>(x, U1, U2, U3);
    epilogue_kernel<<<Bn * SPB, 128>>>(b_e, V_e, out);
}